// round 2
// baseline (speedup 1.0000x reference)
#include <cuda_runtime.h>
#include <cuda_bf16.h>
#include <math.h>

#define NUM_USERS 100000
#define NUM_ITEMS 50000
#define NROWS     150000      // NUM_USERS + NUM_ITEMS
#define NPAD      150016      // padded row count (multiple of 128)
#define EMB       64
#define NEDGES    2400000
#define NLAYERS   3
#define NEG_SLOPE 0.01f

#define SCAN_CHUNK 2048
#define NUM_CHUNKS ((NROWS + SCAN_CHUNK - 1) / SCAN_CHUNK)   // 74

typedef unsigned long long u64;

// packed fp32x2 FMA (Blackwell; ptxas never auto-fuses -> inline PTX)
#define FMA2(d, a, b, c) \
    asm("fma.rn.f32x2 %0, %1, %2, %3;" : "=l"(d) : "l"(a), "l"(b), "l"(c))
#define PACK2(d, lo, hi) \
    asm("mov.b64 %0, {%1, %2};" : "=l"(d) : "f"(lo), "f"(hi))
#define UNPACK2(lo, hi, v) \
    asm("mov.b64 {%0, %1}, %2;" : "=f"(lo), "=f"(hi) : "l"(v))

// -------- persistent device scratch (no allocations allowed) --------
__device__ __align__(16) float g_ego [NPAD * EMB];
__device__ __align__(16) float g_side[NPAD * EMB];
__device__ int   g_row_ptr[NROWS + 1];
__device__ int   g_cursor [NROWS];       // doubles as histogram counts
__device__ int   g_col [NEDGES];
__device__ float g_val [NEDGES];
__device__ int   g_bsum[NUM_CHUNKS];
__device__ int   g_boff[NUM_CHUNKS];

// ---------------------------------------------------------------
// CSR build
// ---------------------------------------------------------------
__global__ void k_zero_counts() {
    int i = blockIdx.x * blockDim.x + threadIdx.x;
    if (i < NROWS) g_cursor[i] = 0;
}

__global__ void k_hist(const int* __restrict__ rows, int n_edges) {
    int e = blockIdx.x * blockDim.x + threadIdx.x;
    if (e < n_edges) atomicAdd(&g_cursor[rows[e]], 1);
}

__global__ void k_scan_sums() {
    int b = blockIdx.x, t = threadIdx.x;
    int base = b * SCAN_CHUNK + t * 8;
    int s = 0;
#pragma unroll
    for (int i = 0; i < 8; i++) {
        int idx = base + i;
        if (idx < NROWS) s += g_cursor[idx];
    }
    __shared__ int sh[256];
    sh[t] = s;
    __syncthreads();
    for (int d = 128; d > 0; d >>= 1) {
        if (t < d) sh[t] += sh[t + d];
        __syncthreads();
    }
    if (t == 0) g_bsum[b] = sh[0];
}

// parallel exclusive scan over NUM_CHUNKS block sums (one 128-thread block)
__global__ void k_scan_top() {
    int t = threadIdx.x;
    __shared__ int sh[128];
    int v = (t < NUM_CHUNKS) ? g_bsum[t] : 0;
    sh[t] = v;
    __syncthreads();
    for (int d = 1; d < 128; d <<= 1) {
        int x = (t >= d) ? sh[t - d] : 0;
        __syncthreads();
        sh[t] += x;
        __syncthreads();
    }
    if (t < NUM_CHUNKS) g_boff[t] = sh[t] - v;           // exclusive
    if (t == NUM_CHUNKS - 1) g_row_ptr[NROWS] = sh[t];   // total
}

__global__ void k_scan_final() {
    int b = blockIdx.x, t = threadIdx.x;
    int base = b * SCAN_CHUNK + t * 8;
    int v[8];
    int local = 0;
#pragma unroll
    for (int i = 0; i < 8; i++) {
        int idx = base + i;
        v[i] = (idx < NROWS) ? g_cursor[idx] : 0;
        local += v[i];
    }
    __shared__ int sh[256];
    sh[t] = local;
    __syncthreads();
    for (int d = 1; d < 256; d <<= 1) {
        int x = (t >= d) ? sh[t - d] : 0;
        __syncthreads();
        sh[t] += x;
        __syncthreads();
    }
    int exc = g_boff[b] + (t ? sh[t - 1] : 0);
#pragma unroll
    for (int i = 0; i < 8; i++) {
        int idx = base + i;
        if (idx < NROWS) {
            g_row_ptr[idx] = exc;
            g_cursor[idx]  = exc;     // scatter cursor (fused: no copy pass)
        }
        exc += v[i];
    }
}

__global__ void k_scatter(const int* __restrict__ rows,
                          const int* __restrict__ cols,
                          const float* __restrict__ vals, int n_edges) {
    int e = blockIdx.x * blockDim.x + threadIdx.x;
    if (e < n_edges) {
        int r = rows[e];
        int pos = atomicAdd(&g_cursor[r], 1);
        g_col[pos] = cols[e];
        g_val[pos] = vals[e];
    }
}

// ---------------------------------------------------------------
// init: ego = [user_emb; item_emb]; out[:, 0:64] = ego
// ---------------------------------------------------------------
__global__ void k_init(const float* __restrict__ user_emb,
                       const float* __restrict__ item_emb,
                       float* __restrict__ out) {
    int idx = blockIdx.x * blockDim.x + threadIdx.x;   // one float4 per thread
    if (idx >= NROWS * 16) return;
    int r = idx >> 4;
    int c4 = idx & 15;
    float4 v;
    if (r < NUM_USERS)
        v = ((const float4*)&user_emb[r * EMB])[c4];
    else
        v = ((const float4*)&item_emb[(r - NUM_USERS) * EMB])[c4];
    ((float4*)&g_ego[r * EMB])[c4] = v;
    ((float4*)&out[r * (EMB * (NLAYERS + 1))])[c4] = v;
}

// ---------------------------------------------------------------
// SpMM: side = A @ ego   (warp per row, 2 edges/iter, LDG.128 gathers)
// lanes 0-15 handle edge i, lanes 16-31 handle edge i+1; lane covers 4 cols
// ---------------------------------------------------------------
__global__ void k_spmm() {
    int w = (blockIdx.x * blockDim.x + threadIdx.x) >> 5;
    if (w >= NROWS) return;
    int lane = threadIdx.x & 31;
    int half = lane >> 4;          // which edge of the pair
    int cl   = lane & 15;          // float4 index within the row

    int s = __ldg(&g_row_ptr[w]);
    int e = __ldg(&g_row_ptr[w + 1]);

    float4 acc = make_float4(0.f, 0.f, 0.f, 0.f);
    int i = s;
#pragma unroll 2
    for (; i + 2 <= e; i += 2) {
        int   c = __ldg(&g_col[i + half]);
        float v = __ldg(&g_val[i + half]);
        float4 x = *(const float4*)&g_ego[c * EMB + cl * 4];
        acc.x = fmaf(v, x.x, acc.x);
        acc.y = fmaf(v, x.y, acc.y);
        acc.z = fmaf(v, x.z, acc.z);
        acc.w = fmaf(v, x.w, acc.w);
    }
    if (i < e && half == 0) {      // odd remainder: half 0 only
        int   c = __ldg(&g_col[i]);
        float v = __ldg(&g_val[i]);
        float4 x = *(const float4*)&g_ego[c * EMB + cl * 4];
        acc.x = fmaf(v, x.x, acc.x);
        acc.y = fmaf(v, x.y, acc.y);
        acc.z = fmaf(v, x.z, acc.z);
        acc.w = fmaf(v, x.w, acc.w);
    }
    // combine the two half-warps
    acc.x += __shfl_xor_sync(0xffffffffu, acc.x, 16);
    acc.y += __shfl_xor_sync(0xffffffffu, acc.y, 16);
    acc.z += __shfl_xor_sync(0xffffffffu, acc.z, 16);
    acc.w += __shfl_xor_sync(0xffffffffu, acc.w, 16);
    if (half == 0)
        *(float4*)&g_side[w * EMB + cl * 4] = acc;
}

// ---------------------------------------------------------------
// Transform: ego = lrelu(side@W1+b1) + lrelu((ego*side)@W2+b2)
//            out[:, (l+1)*64 : (l+2)*64] = ego / max(||ego||, eps)
// thread-per-row; W broadcast from shared; packed f32x2 FMA
// ---------------------------------------------------------------
__device__ __forceinline__ float lrelu(float a) {
    return (a > 0.f) ? a : NEG_SLOPE * a;
}

__global__ void __launch_bounds__(128)
k_transform(const float* __restrict__ W1g, const float* __restrict__ b1g,
            const float* __restrict__ W2g, const float* __restrict__ b2g,
            float* __restrict__ out, int layer) {
    extern __shared__ float sh[];
    float* W1s   = sh;                 // 4096
    float* W2s   = sh + 4096;          // 4096
    float* b1s   = sh + 8192;          // 64
    float* b2s   = sh + 8256;          // 64
    float* sideS = sh + 8320;          // 128*65 = 8320
    float* uS    = sideS + 128 * 65;   // 8320

    int t = threadIdx.x;
    int base = blockIdx.x * 128;

    // load weights (coalesced float4)
#pragma unroll 4
    for (int i = t; i < 1024; i += 128) {
        ((float4*)W1s)[i] = ((const float4*)W1g)[i];
        ((float4*)W2s)[i] = ((const float4*)W2g)[i];
    }
    if (t < 64) { b1s[t] = b1g[t]; b2s[t] = b2g[t]; }

    // stage side + u = ego*side for the block's 128 rows (padded stride 65)
    const float4* sg = (const float4*)&g_side[(size_t)base * EMB];
    const float4* eg = (const float4*)&g_ego [(size_t)base * EMB];
#pragma unroll 4
    for (int i = t; i < 2048; i += 128) {
        float4 sv = sg[i];
        float4 ev = eg[i];
        int row = i >> 4;
        int c = (i & 15) * 4;
        float* ds = &sideS[row * 65 + c];
        float* du = &uS   [row * 65 + c];
        ds[0] = sv.x; ds[1] = sv.y; ds[2] = sv.z; ds[3] = sv.w;
        du[0] = ev.x * sv.x; du[1] = ev.y * sv.y;
        du[2] = ev.z * sv.z; du[3] = ev.w * sv.w;
    }
    __syncthreads();

    int r = base + t;
    if (r >= NROWS) return;

    const float* srow = &sideS[t * 65];
    const float* urow = &uS[t * 65];

    float outv[64];
    float sumsq = 0.f;

#pragma unroll
    for (int h = 0; h < 2; h++) {          // output halves: cols h*32..h*32+31
        u64 acc1[16], acc2[16];
#pragma unroll
        for (int j = 0; j < 16; j++) {
            PACK2(acc1[j], b1s[h * 32 + 2 * j], b1s[h * 32 + 2 * j + 1]);
            PACK2(acc2[j], b2s[h * 32 + 2 * j], b2s[h * 32 + 2 * j + 1]);
        }
#pragma unroll 4
        for (int k = 0; k < 64; k++) {
            float s = srow[k];
            float u = urow[k];
            u64 ss, uu;
            PACK2(ss, s, s);
            PACK2(uu, u, u);
            const u64* w1 = (const u64*)&W1s[k * 64 + h * 32];
            const u64* w2 = (const u64*)&W2s[k * 64 + h * 32];
#pragma unroll
            for (int j = 0; j < 16; j += 2) {
                ulonglong2 a = *(const ulonglong2*)&w1[j];
                FMA2(acc1[j],     ss, a.x, acc1[j]);
                FMA2(acc1[j + 1], ss, a.y, acc1[j + 1]);
                ulonglong2 b = *(const ulonglong2*)&w2[j];
                FMA2(acc2[j],     uu, b.x, acc2[j]);
                FMA2(acc2[j + 1], uu, b.y, acc2[j + 1]);
            }
        }
#pragma unroll
        for (int j = 0; j < 16; j++) {
            float a0, a1, b0, b1;
            UNPACK2(a0, a1, acc1[j]);
            UNPACK2(b0, b1, acc2[j]);
            float o0 = lrelu(a0) + lrelu(b0);
            float o1 = lrelu(a1) + lrelu(b1);
            sumsq += o0 * o0 + o1 * o1;
            outv[h * 32 + 2 * j]     = o0;
            outv[h * 32 + 2 * j + 1] = o1;
        }
    }

    float inv = 1.0f / fmaxf(sqrtf(sumsq), 1e-12f);
    float* egor = &g_ego[(size_t)r * EMB];
    float4* orow = (float4*)&out[(size_t)r * (EMB * (NLAYERS + 1)) + (layer + 1) * EMB];
#pragma unroll
    for (int j4 = 0; j4 < 16; j4++) {
        float4 v = make_float4(outv[j4 * 4], outv[j4 * 4 + 1],
                               outv[j4 * 4 + 2], outv[j4 * 4 + 3]);
        ((float4*)egor)[j4] = v;
        v.x *= inv; v.y *= inv; v.z *= inv; v.w *= inv;
        orow[j4] = v;
    }
}

// ---------------------------------------------------------------
extern "C" void kernel_launch(void* const* d_in, const int* in_sizes, int n_in,
                              void* d_out, int out_size) {
    const int*   adj_rows = (const int*)  d_in[0];
    const int*   adj_cols = (const int*)  d_in[1];
    const float* adj_vals = (const float*)d_in[2];
    const float* user_emb = (const float*)d_in[3];
    const float* item_emb = (const float*)d_in[4];
    const float* gc_w     = (const float*)d_in[5];
    const float* gc_b     = (const float*)d_in[6];
    const float* bi_w     = (const float*)d_in[7];
    const float* bi_b     = (const float*)d_in[8];
    float*       out      = (float*)d_out;

    int n_edges = in_sizes[0];

    const int smem_bytes = (4096 * 2 + 64 * 2 + 128 * 65 * 2) * (int)sizeof(float); // 99840
    cudaFuncSetAttribute(k_transform, cudaFuncAttributeMaxDynamicSharedMemorySize, smem_bytes);

    // ---- CSR build ----
    k_zero_counts<<<(NROWS + 255) / 256, 256>>>();
    k_hist<<<(n_edges + 255) / 256, 256>>>(adj_rows, n_edges);
    k_scan_sums<<<NUM_CHUNKS, 256>>>();
    k_scan_top<<<1, 128>>>();
    k_scan_final<<<NUM_CHUNKS, 256>>>();
    k_scatter<<<(n_edges + 255) / 256, 256>>>(adj_rows, adj_cols, adj_vals, n_edges);

    // ---- init ego + layer-0 output ----
    k_init<<<(NROWS * 16 + 255) / 256, 256>>>(user_emb, item_emb, out);

    // ---- layers ----
    int spmm_blocks = (NROWS * 32 + 255) / 256;        // warp per row
    int tr_blocks   = (NROWS + 127) / 128;
    for (int l = 0; l < NLAYERS; l++) {
        k_spmm<<<spmm_blocks, 256>>>();
        k_transform<<<tr_blocks, 128, smem_bytes>>>(
            gc_w + l * 4096, gc_b + l * 64,
            bi_w + l * 4096, bi_b + l * 64,
            out, l);
    }
}

// round 3
// speedup vs baseline: 1.0757x; 1.0757x over previous
#include <cuda_runtime.h>
#include <cuda_bf16.h>
#include <math.h>

#define NUM_USERS 100000
#define NUM_ITEMS 50000
#define NROWS     150000      // NUM_USERS + NUM_ITEMS
#define NPAD      150016      // padded row count (multiple of 128)
#define EMB       64
#define NEDGES    2400000
#define NLAYERS   3
#define NEG_SLOPE 0.01f

#define SCAN_CHUNK 2048
#define NUM_CHUNKS ((NROWS + SCAN_CHUNK - 1) / SCAN_CHUNK)   // 74

typedef unsigned long long u64;

// packed fp32x2 FMA (Blackwell; ptxas never auto-fuses -> inline PTX)
#define FMA2(d, a, b, c) \
    asm("fma.rn.f32x2 %0, %1, %2, %3;" : "=l"(d) : "l"(a), "l"(b), "l"(c))
#define PACK2(d, lo, hi) \
    asm("mov.b64 %0, {%1, %2};" : "=l"(d) : "f"(lo), "f"(hi))
#define UNPACK2(lo, hi, v) \
    asm("mov.b64 {%0, %1}, %2;" : "=f"(lo), "=f"(hi) : "l"(v))

// -------- persistent device scratch (no allocations allowed) --------
__device__ __align__(16) float g_ego [NPAD * EMB];
__device__ __align__(16) float g_side[NPAD * EMB];
__device__ int   g_row_ptr[NROWS + 1];
__device__ int   g_cursor [NROWS];       // doubles as histogram counts
__device__ int   g_col [NEDGES];
__device__ float g_val [NEDGES];
__device__ int   g_bsum[NUM_CHUNKS];
__device__ int   g_boff[NUM_CHUNKS];

// ---------------------------------------------------------------
// CSR build
// ---------------------------------------------------------------
__global__ void k_zero_counts() {
    int i = blockIdx.x * blockDim.x + threadIdx.x;
    if (i < NROWS) g_cursor[i] = 0;
}

__global__ void k_hist(const int* __restrict__ rows, int n_edges) {
    int e = blockIdx.x * blockDim.x + threadIdx.x;
    if (e < n_edges) atomicAdd(&g_cursor[rows[e]], 1);
}

__global__ void k_scan_sums() {
    int b = blockIdx.x, t = threadIdx.x;
    int base = b * SCAN_CHUNK + t * 8;
    int s = 0;
#pragma unroll
    for (int i = 0; i < 8; i++) {
        int idx = base + i;
        if (idx < NROWS) s += g_cursor[idx];
    }
    __shared__ int sh[256];
    sh[t] = s;
    __syncthreads();
    for (int d = 128; d > 0; d >>= 1) {
        if (t < d) sh[t] += sh[t + d];
        __syncthreads();
    }
    if (t == 0) g_bsum[b] = sh[0];
}

// parallel exclusive scan over NUM_CHUNKS block sums (one 128-thread block)
__global__ void k_scan_top() {
    int t = threadIdx.x;
    __shared__ int sh[128];
    int v = (t < NUM_CHUNKS) ? g_bsum[t] : 0;
    sh[t] = v;
    __syncthreads();
    for (int d = 1; d < 128; d <<= 1) {
        int x = (t >= d) ? sh[t - d] : 0;
        __syncthreads();
        sh[t] += x;
        __syncthreads();
    }
    if (t < NUM_CHUNKS) g_boff[t] = sh[t] - v;           // exclusive
    if (t == NUM_CHUNKS - 1) g_row_ptr[NROWS] = sh[t];   // total
}

__global__ void k_scan_final() {
    int b = blockIdx.x, t = threadIdx.x;
    int base = b * SCAN_CHUNK + t * 8;
    int v[8];
    int local = 0;
#pragma unroll
    for (int i = 0; i < 8; i++) {
        int idx = base + i;
        v[i] = (idx < NROWS) ? g_cursor[idx] : 0;
        local += v[i];
    }
    __shared__ int sh[256];
    sh[t] = local;
    __syncthreads();
    for (int d = 1; d < 256; d <<= 1) {
        int x = (t >= d) ? sh[t - d] : 0;
        __syncthreads();
        sh[t] += x;
        __syncthreads();
    }
    int exc = g_boff[b] + (t ? sh[t - 1] : 0);
#pragma unroll
    for (int i = 0; i < 8; i++) {
        int idx = base + i;
        if (idx < NROWS) {
            g_row_ptr[idx] = exc;
            g_cursor[idx]  = exc;     // scatter cursor (fused: no copy pass)
        }
        exc += v[i];
    }
}

__global__ void k_scatter(const int* __restrict__ rows,
                          const int* __restrict__ cols,
                          const float* __restrict__ vals, int n_edges) {
    int e = blockIdx.x * blockDim.x + threadIdx.x;
    if (e < n_edges) {
        int r = rows[e];
        int pos = atomicAdd(&g_cursor[r], 1);
        g_col[pos] = cols[e];
        g_val[pos] = vals[e];
    }
}

// ---------------------------------------------------------------
// init: ego = [user_emb; item_emb]; out[:, 0:64] = ego
// ---------------------------------------------------------------
__global__ void k_init(const float* __restrict__ user_emb,
                       const float* __restrict__ item_emb,
                       float* __restrict__ out) {
    int idx = blockIdx.x * blockDim.x + threadIdx.x;   // one float4 per thread
    if (idx >= NROWS * 16) return;
    int r = idx >> 4;
    int c4 = idx & 15;
    float4 v;
    if (r < NUM_USERS)
        v = ((const float4*)&user_emb[r * EMB])[c4];
    else
        v = ((const float4*)&item_emb[(r - NUM_USERS) * EMB])[c4];
    ((float4*)&g_ego[r * EMB])[c4] = v;
    ((float4*)&out[r * (EMB * (NLAYERS + 1))])[c4] = v;
}

// ---------------------------------------------------------------
// SpMM: side = A @ ego   (warp per row, CSR, no atomics) — R1 proven version
// ---------------------------------------------------------------
__global__ void k_spmm() {
    int w = (blockIdx.x * blockDim.x + threadIdx.x) >> 5;
    int lane = threadIdx.x & 31;
    if (w >= NROWS) return;
    int s = g_row_ptr[w];
    int e = g_row_ptr[w + 1];
    float2 acc = make_float2(0.f, 0.f);
    for (int i = s; i < e; i++) {
        int c = __ldg(&g_col[i]);
        float v = __ldg(&g_val[i]);
        float2 x = *(const float2*)&g_ego[c * EMB + lane * 2];
        acc.x = fmaf(v, x.x, acc.x);
        acc.y = fmaf(v, x.y, acc.y);
    }
    *(float2*)&g_side[w * EMB + lane * 2] = acc;
}

// ---------------------------------------------------------------
// Transform: ego = lrelu(side@W1+b1) + lrelu((ego*side)@W2+b2)
//            out[:, (l+1)*64 : (l+2)*64] = ego / max(||ego||, eps)
// 256 threads per 128 rows: thread computes 32 output cols of one row.
// threads 0-127: cols 0-31 of rows base..base+127; threads 128-255: cols 32-63.
// W broadcast from shared (warp-uniform addresses); packed f32x2 FMA.
// ---------------------------------------------------------------
__device__ __forceinline__ float lrelu(float a) {
    return (a > 0.f) ? a : NEG_SLOPE * a;
}

__global__ void __launch_bounds__(256)
k_transform(const float* __restrict__ W1g, const float* __restrict__ b1g,
            const float* __restrict__ W2g, const float* __restrict__ b2g,
            float* __restrict__ out, int layer) {
    extern __shared__ float sh[];
    float* W1s   = sh;                 // 4096
    float* W2s   = sh + 4096;          // 4096
    float* b1s   = sh + 8192;          // 64
    float* b2s   = sh + 8256;          // 64
    float* ssq   = sh + 8320;          // 256 partial sumsq
    float* sideS = sh + 8576;          // 128*65 = 8320
    float* uS    = sideS + 128 * 65;   // 8320
    // total = 25216 floats = 100864 bytes

    int t = threadIdx.x;
    int base = blockIdx.x * 128;

    // load weights (coalesced float4)
#pragma unroll 4
    for (int i = t; i < 1024; i += 256) {
        ((float4*)W1s)[i] = ((const float4*)W1g)[i];
        ((float4*)W2s)[i] = ((const float4*)W2g)[i];
    }
    if (t < 64) { b1s[t] = b1g[t]; b2s[t] = b2g[t]; }

    // stage side + u = ego*side for the block's 128 rows (padded stride 65)
    const float4* sg = (const float4*)&g_side[(size_t)base * EMB];
    const float4* eg = (const float4*)&g_ego [(size_t)base * EMB];
#pragma unroll 4
    for (int i = t; i < 2048; i += 256) {
        float4 sv = sg[i];
        float4 ev = eg[i];
        int row = i >> 4;
        int c = (i & 15) * 4;
        float* ds = &sideS[row * 65 + c];
        float* du = &uS   [row * 65 + c];
        ds[0] = sv.x; ds[1] = sv.y; ds[2] = sv.z; ds[3] = sv.w;
        du[0] = ev.x * sv.x; du[1] = ev.y * sv.y;
        du[2] = ev.z * sv.z; du[3] = ev.w * sv.w;
    }
    __syncthreads();

    int row = t & 127;        // row within block
    int h   = t >> 7;         // output half: 0 -> cols 0-31, 1 -> cols 32-63
    int r   = base + row;

    float o[32];              // this thread's 32 outputs (unnormalized)

    if (r < NROWS) {
        const float* srow = &sideS[row * 65];
        const float* urow = &uS[row * 65];

        u64 acc1[16], acc2[16];
#pragma unroll
        for (int j = 0; j < 16; j++) {
            PACK2(acc1[j], b1s[h * 32 + 2 * j], b1s[h * 32 + 2 * j + 1]);
            PACK2(acc2[j], b2s[h * 32 + 2 * j], b2s[h * 32 + 2 * j + 1]);
        }
#pragma unroll 4
        for (int k = 0; k < 64; k++) {
            float s = srow[k];
            float u = urow[k];
            u64 ss, uu;
            PACK2(ss, s, s);
            PACK2(uu, u, u);
            const u64* w1 = (const u64*)&W1s[k * 64 + h * 32];
            const u64* w2 = (const u64*)&W2s[k * 64 + h * 32];
#pragma unroll
            for (int j = 0; j < 16; j += 2) {
                ulonglong2 a = *(const ulonglong2*)&w1[j];
                FMA2(acc1[j],     ss, a.x, acc1[j]);
                FMA2(acc1[j + 1], ss, a.y, acc1[j + 1]);
                ulonglong2 b = *(const ulonglong2*)&w2[j];
                FMA2(acc2[j],     uu, b.x, acc2[j]);
                FMA2(acc2[j + 1], uu, b.y, acc2[j + 1]);
            }
        }

        float sumsq = 0.f;
#pragma unroll
        for (int j = 0; j < 16; j++) {
            float a0, a1, b0, b1;
            UNPACK2(a0, a1, acc1[j]);
            UNPACK2(b0, b1, acc2[j]);
            float o0 = lrelu(a0) + lrelu(b0);
            float o1 = lrelu(a1) + lrelu(b1);
            sumsq += o0 * o0 + o1 * o1;
            o[2 * j]     = o0;
            o[2 * j + 1] = o1;
        }
        ssq[t] = sumsq;   // t = h*128 + row

        // write unnormalized half-row to g_ego
        float4* egor = (float4*)&g_ego[(size_t)r * EMB + h * 32];
#pragma unroll
        for (int j4 = 0; j4 < 8; j4++)
            egor[j4] = make_float4(o[j4 * 4], o[j4 * 4 + 1],
                                   o[j4 * 4 + 2], o[j4 * 4 + 3]);
    }
    __syncthreads();

    if (r < NROWS) {
        float total = ssq[row] + ssq[128 + row];
        float inv = 1.0f / fmaxf(sqrtf(total), 1e-12f);
        float4* orow = (float4*)&out[(size_t)r * (EMB * (NLAYERS + 1))
                                     + (layer + 1) * EMB + h * 32];
#pragma unroll
        for (int j4 = 0; j4 < 8; j4++)
            orow[j4] = make_float4(o[j4 * 4] * inv, o[j4 * 4 + 1] * inv,
                                   o[j4 * 4 + 2] * inv, o[j4 * 4 + 3] * inv);
    }
}

// ---------------------------------------------------------------
extern "C" void kernel_launch(void* const* d_in, const int* in_sizes, int n_in,
                              void* d_out, int out_size) {
    const int*   adj_rows = (const int*)  d_in[0];
    const int*   adj_cols = (const int*)  d_in[1];
    const float* adj_vals = (const float*)d_in[2];
    const float* user_emb = (const float*)d_in[3];
    const float* item_emb = (const float*)d_in[4];
    const float* gc_w     = (const float*)d_in[5];
    const float* gc_b     = (const float*)d_in[6];
    const float* bi_w     = (const float*)d_in[7];
    const float* bi_b     = (const float*)d_in[8];
    float*       out      = (float*)d_out;

    int n_edges = in_sizes[0];

    const int smem_bytes = 25216 * (int)sizeof(float); // 100864
    cudaFuncSetAttribute(k_transform, cudaFuncAttributeMaxDynamicSharedMemorySize, smem_bytes);

    // ---- CSR build ----
    k_zero_counts<<<(NROWS + 255) / 256, 256>>>();
    k_hist<<<(n_edges + 255) / 256, 256>>>(adj_rows, n_edges);
    k_scan_sums<<<NUM_CHUNKS, 256>>>();
    k_scan_top<<<1, 128>>>();
    k_scan_final<<<NUM_CHUNKS, 256>>>();
    k_scatter<<<(n_edges + 255) / 256, 256>>>(adj_rows, adj_cols, adj_vals, n_edges);

    // ---- init ego + layer-0 output ----
    k_init<<<(NROWS * 16 + 255) / 256, 256>>>(user_emb, item_emb, out);

    // ---- layers ----
    int spmm_blocks = (NROWS * 32 + 255) / 256;        // warp per row
    int tr_blocks   = (NROWS + 127) / 128;
    for (int l = 0; l < NLAYERS; l++) {
        k_spmm<<<spmm_blocks, 256>>>();
        k_transform<<<tr_blocks, 256, smem_bytes>>>(
            gc_w + l * 4096, gc_b + l * 64,
            bi_w + l * 4096, bi_b + l * 64,
            out, l);
    }
}